// round 5
// baseline (speedup 1.0000x reference)
#include <cuda_runtime.h>

// out[e] = dot(h[src[e]], h[dst[e]]); h: [N,128] fp32, E ~3.2M, int32 idx.
//
// Register-lean direct gather: 16 lanes per edge, 2 edges per warp.
// Each lane loads 2 float4 from the src row and 2 from the dst row
// (interleaved mapping f4 = sub + 16*j -> each LDG covers dense 128B lines,
// 512B per warp-instruction). 4 in-flight LDG.128 per lane; low reg count
// lets 7 blocks/SM reside (56 warps) vs 5 previously.
// Persistent grid-stride loop + index prefetch.

#define F4_PER_ROW 32   // 128 floats = 32 float4

__global__ void __launch_bounds__(256, 7)
edge_dot_kernel(const float4* __restrict__ h4,
                const int* __restrict__ src,
                const int* __restrict__ dst,
                float* __restrict__ out,
                int n_edges)
{
    const int lane  = threadIdx.x & 31;
    const int group = lane >> 4;       // 0..1: edge slot within warp
    const int sub   = lane & 15;       // 0..15: lane within edge group

    const int warp_id  = (blockIdx.x * blockDim.x + threadIdx.x) >> 5;
    const int n_warps  = (gridDim.x * blockDim.x) >> 5;
    const int e_stride = n_warps * 2;

    int e = warp_id * 2 + group;

    int s_pre = 0, d_pre = 0;
    if (e < n_edges) {
        s_pre = __ldg(&src[e]);
        d_pre = __ldg(&dst[e]);
    }

    for (; e < n_edges; e += e_stride) {
        const int s = s_pre;
        const int d = d_pre;

        const int e_next = e + e_stride;
        if (e_next < n_edges) {
            s_pre = __ldg(&src[e_next]);
            d_pre = __ldg(&dst[e_next]);
        }

        const float4* __restrict__ hs = h4 + (size_t)s * F4_PER_ROW;
        const float4* __restrict__ hd = h4 + (size_t)d * F4_PER_ROW;

        // 4 independent 16B loads per lane (2 rows x 2 chunks)
        float4 a0 = __ldg(&hs[sub +  0]);
        float4 a1 = __ldg(&hs[sub + 16]);
        float4 b0 = __ldg(&hd[sub +  0]);
        float4 b1 = __ldg(&hd[sub + 16]);

        float sum;
        sum = a0.x * b0.x;
        sum = fmaf(a0.y, b0.y, sum);
        sum = fmaf(a0.z, b0.z, sum);
        sum = fmaf(a0.w, b0.w, sum);
        sum = fmaf(a1.x, b1.x, sum);
        sum = fmaf(a1.y, b1.y, sum);
        sum = fmaf(a1.z, b1.z, sum);
        sum = fmaf(a1.w, b1.w, sum);

        // Reduce within 16-lane group
        sum += __shfl_xor_sync(0xFFFFFFFFu, sum, 8);
        sum += __shfl_xor_sync(0xFFFFFFFFu, sum, 4);
        sum += __shfl_xor_sync(0xFFFFFFFFu, sum, 2);
        sum += __shfl_xor_sync(0xFFFFFFFFu, sum, 1);

        if (sub == 0)
            out[e] = sum;
    }
}

extern "C" void kernel_launch(void* const* d_in, const int* in_sizes, int n_in,
                              void* d_out, int out_size)
{
    const float4* h4  = (const float4*)d_in[0];
    const int*    src = (const int*)d_in[1];
    const int*    dst = (const int*)d_in[2];
    float*        out = (float*)d_out;

    const int n_edges = in_sizes[1];

    // 7 blocks/SM x 148 SMs = 1036 persistent blocks.
    const int blocks = 1036;
    edge_dot_kernel<<<blocks, 256>>>(h4, src, dst, out, n_edges);
}